// round 2
// baseline (speedup 1.0000x reference)
#include <cuda_runtime.h>

#define N_  128
#define C_  64
#define T_  288
#define V_  16
#define S_  3
#define IC_ 16

// tiny scratch: attention matrices after softmax + A  [N, S, V, V]
__device__ float g_att[N_ * S_ * V_ * V_];

// ---------------------------------------------------------------------------
// Kernel A: per (n, s) compute att[v][w] = softmax_v( (1/(IC*T)) * sum_{i,t}
//   fa[i,t,v] * fb[i,t,w] ) + (A_base + PA)[s,v,w]
// fa[i,t,v] = sum_c Wa[s,i,c] x[n,c,t,v] + ba[s,i]   (fb analogous)
// x streamed through smem in chunks of 8 t's; fa/fb never touch HBM.
// ---------------------------------------------------------------------------
__global__ __launch_bounds__(256, 3) void attn_kernel(
    const float* __restrict__ x, const float* __restrict__ A_base,
    const float* __restrict__ PA, const float* __restrict__ Wa,
    const float* __restrict__ ba, const float* __restrict__ Wb,
    const float* __restrict__ bb)
{
    extern __shared__ float smem[];
    float* sWaT = smem;               // [64][16]  (c-major, i inner)
    float* sWbT = sWaT + 1024;        // [64][16]
    float* sX   = sWbT + 1024;        // [64][128] (c rows, 8t*16v contiguous)
    float* sfa  = sX + 8192;          // [16][128] (i rows)
    float* sfb  = sfa + 2048;         // [16][128]

    __shared__ float satt[256];
    __shared__ float sbias[32];
    __shared__ float colmax[16], colinv[16];

    const int tid = threadIdx.x;
    const int n = blockIdx.x / S_;
    const int s = blockIdx.x % S_;

    for (int idx = tid; idx < IC_ * C_; idx += 256) {
        int i = idx >> 6, c = idx & 63;
        sWaT[c * 16 + i] = Wa[(s * IC_ + i) * C_ + c];
        sWbT[c * 16 + i] = Wb[(s * IC_ + i) * C_ + c];
    }
    if (tid < 16)      sbias[tid] = ba[s * 16 + tid];
    else if (tid < 32) sbias[tid] = bb[s * 16 + (tid - 16)];
    __syncthreads();

    const float* xn = x + (size_t)n * (C_ * T_ * V_);

    const int j = tid & 127;       // column within chunk (tt*16 + v)
    const int g = tid >> 7;        // 0 -> fa, 1 -> fb
    const float* WT = g ? sWbT : sWaT;
    float* F = g ? sfb : sfa;

    const int v = tid >> 4;        // att row
    const int w = tid & 15;        // att col
    float attacc = 0.f;

    for (int t0 = 0; t0 < T_; t0 += 8) {
        // load x[n, :, t0:t0+8, :] -> sX  (each c-row is 128 contiguous floats)
        for (int idx = tid; idx < 64 * 32; idx += 256) {
            int c = idx >> 5, q = idx & 31;
            reinterpret_cast<float4*>(sX + c * 128)[q] =
                reinterpret_cast<const float4*>(xn + (size_t)c * (T_ * V_) + t0 * V_)[q];
        }
        __syncthreads();

        // fa/fb chunk: 128 threads per array, each thread one column, all 16 i
        {
            float acc[16];
            #pragma unroll
            for (int i = 0; i < 16; i++) acc[i] = sbias[g * 16 + i];
            #pragma unroll 4
            for (int c = 0; c < 64; c++) {
                float xv = sX[c * 128 + j];
                const float4* w4 = reinterpret_cast<const float4*>(WT + c * 16);
                #pragma unroll
                for (int q = 0; q < 4; q++) {
                    float4 a = w4[q];
                    acc[q * 4 + 0] += a.x * xv;
                    acc[q * 4 + 1] += a.y * xv;
                    acc[q * 4 + 2] += a.z * xv;
                    acc[q * 4 + 3] += a.w * xv;
                }
            }
            #pragma unroll
            for (int i = 0; i < 16; i++) F[i * 128 + j] = acc[i];
        }
        __syncthreads();

        // att[v][w] += sum_{i, tt} fa[i][tt*16+v] * fb[i][tt*16+w]
        #pragma unroll
        for (int i = 0; i < 16; i++) {
            #pragma unroll
            for (int tt = 0; tt < 8; tt++) {
                attacc += sfa[i * 128 + tt * 16 + v] * sfb[i * 128 + tt * 16 + w];
            }
        }
        __syncthreads();
    }

    attacc *= (1.0f / (float)(IC_ * T_));
    satt[v * 16 + w] = attacc;
    __syncthreads();

    // softmax over v (per column w)
    if (tid < 16) {
        float m = -1e30f;
        #pragma unroll
        for (int vv = 0; vv < 16; vv++) m = fmaxf(m, satt[vv * 16 + tid]);
        float ssum = 0.f;
        #pragma unroll
        for (int vv = 0; vv < 16; vv++) ssum += __expf(satt[vv * 16 + tid] - m);
        colmax[tid] = m;
        colinv[tid] = 1.0f / ssum;
    }
    __syncthreads();

    float r = __expf(attacc - colmax[w]) * colinv[w]
            + A_base[(s * 16 + v) * 16 + w] + PA[(s * 16 + v) * 16 + w];
    g_att[((n * 3 + s) * 16 + v) * 16 + w] = r;
}

// ---------------------------------------------------------------------------
// Kernel B: per (n, 8-t tile):
//   stage1: tmp[s,c,w] = sum_v x[n,c,t,v] * att[n,s,v,w]     (z, per t)
//   stage2: y[o,t,w]   = sum_{s,c} Wd[s,o,c] * tmp[s,c,w]
//   epilogue: y = (y + sum_s bd[s,o]) * gamma[o]/sqrt(1+eps) + beta[o] + x
// sTmp is double-buffered on tt parity so only one barrier per tt is needed.
// ---------------------------------------------------------------------------
__global__ __launch_bounds__(256, 2) void out_kernel(
    const float* __restrict__ x, const float* __restrict__ Wd,
    const float* __restrict__ bd, const float* __restrict__ gamma,
    const float* __restrict__ beta, float* __restrict__ out)
{
    extern __shared__ float smem[];
    float* sWdT = smem;                 // [3][64][68]  (s, c rows, o inner, padded)
    float* sAtt = sWdT + 3 * 64 * 68;   // [3][16][16]
    float* sX   = sAtt + 768;           // [64][128]
    float* sTmp = sX + 8192;            // 2 x [3][64][16] (ping-pong)

    const int tid = threadIdx.x;
    const int n  = blockIdx.y;
    const int t0 = blockIdx.x * 8;

    // Wd transposed into smem: sWdT[s][c][o]
    for (int idx = tid; idx < S_ * C_ * C_; idx += 256) {
        int s = idx >> 12;
        int rem = idx & 4095;
        int o = rem >> 6;
        int c = rem & 63;
        sWdT[(s * 64 + c) * 68 + o] = Wd[idx];
    }
    for (int idx = tid; idx < 768; idx += 256)
        sAtt[idx] = g_att[n * 768 + idx];
    for (int idx = tid; idx < 64 * 32; idx += 256) {
        int c = idx >> 5, q = idx & 31;
        reinterpret_cast<float4*>(sX + c * 128)[q] =
            reinterpret_cast<const float4*>(x + (size_t)(n * 64 + c) * (T_ * V_) + t0 * V_)[q];
    }

    // per-thread epilogue constants (thread owns o = og*4 .. og*4+3, column w)
    const int w  = tid & 15;
    const int og = tid >> 4;
    float bds[4], scl[4], bet[4];
    const float bn_inv = rsqrtf(1.0f + 1e-5f);
    #pragma unroll
    for (int jj = 0; jj < 4; jj++) {
        int o = og * 4 + jj;
        bds[jj] = bd[o] + bd[64 + o] + bd[128 + o];
        scl[jj] = gamma[o] * bn_inv;
        bet[jj] = beta[o];
    }
    __syncthreads();

    const int c1 = tid >> 2;   // stage1: channel row
    const int wg = tid & 3;    // stage1: group of 4 w's

    // prologue: stage1 for tt=0 into buffer 0
    {
        float xr[16];
        const float4* xp = reinterpret_cast<const float4*>(sX + c1 * 128);
        #pragma unroll
        for (int q = 0; q < 4; q++) {
            float4 xx = xp[q];
            xr[q * 4 + 0] = xx.x; xr[q * 4 + 1] = xx.y;
            xr[q * 4 + 2] = xx.z; xr[q * 4 + 3] = xx.w;
        }
        #pragma unroll
        for (int s = 0; s < 3; s++) {
            float4 acc = make_float4(0.f, 0.f, 0.f, 0.f);
            #pragma unroll
            for (int vv = 0; vv < 16; vv++) {
                float4 a = reinterpret_cast<const float4*>(sAtt + (s * 16 + vv) * 16)[wg];
                float xv = xr[vv];
                acc.x += xv * a.x; acc.y += xv * a.y;
                acc.z += xv * a.z; acc.w += xv * a.w;
            }
            reinterpret_cast<float4*>(sTmp + (s * 64 + c1) * 16)[wg] = acc;
        }
    }
    __syncthreads();

    for (int tt = 0; tt < 8; tt++) {
        float* curTmp  = sTmp + (tt & 1) * 3072;
        float* nextTmp = sTmp + ((tt + 1) & 1) * 3072;

        // ---- stage1 for tt+1 into the other buffer (overlaps with stage2 tt)
        if (tt < 7) {
            float xr[16];
            const float4* xp = reinterpret_cast<const float4*>(sX + c1 * 128 + (tt + 1) * 16);
            #pragma unroll
            for (int q = 0; q < 4; q++) {
                float4 xx = xp[q];
                xr[q * 4 + 0] = xx.x; xr[q * 4 + 1] = xx.y;
                xr[q * 4 + 2] = xx.z; xr[q * 4 + 3] = xx.w;
            }
            #pragma unroll
            for (int s = 0; s < 3; s++) {
                float4 acc = make_float4(0.f, 0.f, 0.f, 0.f);
                #pragma unroll
                for (int vv = 0; vv < 16; vv++) {
                    float4 a = reinterpret_cast<const float4*>(sAtt + (s * 16 + vv) * 16)[wg];
                    float xv = xr[vv];
                    acc.x += xv * a.x; acc.y += xv * a.y;
                    acc.z += xv * a.z; acc.w += xv * a.w;
                }
                reinterpret_cast<float4*>(nextTmp + (s * 64 + c1) * 16)[wg] = acc;
            }
        }

        // ---- stage2: y[og*4..+3][w] = sum_{s,c} WdT[s][c][o] * tmp[s][c][w]
        {
            float4 y = make_float4(0.f, 0.f, 0.f, 0.f);
            #pragma unroll
            for (int s = 0; s < 3; s++) {
                const float* tp = curTmp + s * 1024 + w;
                const float* wp = sWdT + s * 4352 + og * 4;
                #pragma unroll 8
                for (int c = 0; c < 64; c++) {
                    float tv = tp[c * 16];
                    float4 wd = *reinterpret_cast<const float4*>(wp + c * 68);
                    y.x += wd.x * tv; y.y += wd.y * tv;
                    y.z += wd.z * tv; y.w += wd.w * tv;
                }
            }
            const int t = t0 + tt;
            const size_t base = ((size_t)(n * 64 + og * 4) * T_ + t) * V_ + w;
            float vals[4] = {y.x, y.y, y.z, y.w};
            #pragma unroll
            for (int jj = 0; jj < 4; jj++) {
                size_t idx = base + (size_t)jj * (T_ * V_);
                out[idx] = (vals[jj] + bds[jj]) * scl[jj] + bet[jj] + x[idx];
            }
        }
        __syncthreads();
    }
}

extern "C" void kernel_launch(void* const* d_in, const int* in_sizes, int n_in,
                              void* d_out, int out_size)
{
    const float* x      = (const float*)d_in[0];
    const float* A_base = (const float*)d_in[1];
    const float* PA     = (const float*)d_in[2];
    const float* Wa     = (const float*)d_in[3];
    const float* ba     = (const float*)d_in[4];
    const float* Wb     = (const float*)d_in[5];
    const float* bb     = (const float*)d_in[6];
    const float* Wd     = (const float*)d_in[7];
    const float* bd     = (const float*)d_in[8];
    const float* gamma  = (const float*)d_in[9];
    const float* beta   = (const float*)d_in[10];
    float* out = (float*)d_out;

    const int smemA = (1024 * 2 + 8192 + 2048 * 2) * sizeof(float);            // 57344 B
    const int smemB = (3 * 64 * 68 + 768 + 8192 + 2 * 3072) * sizeof(float);   // 112640 B

    cudaFuncSetAttribute(attn_kernel, cudaFuncAttributeMaxDynamicSharedMemorySize, smemA);
    cudaFuncSetAttribute(out_kernel,  cudaFuncAttributeMaxDynamicSharedMemorySize, smemB);

    attn_kernel<<<N_ * S_, 256, smemA>>>(x, A_base, PA, Wa, ba, Wb, bb);
    out_kernel<<<dim3(T_ / 8, N_), 256, smemB>>>(x, Wd, bd, gamma, beta, out);
}

// round 3
// speedup vs baseline: 1.3152x; 1.3152x over previous
#include <cuda_runtime.h>

#define N_  128
#define C_  64
#define T_  288
#define V_  16
#define S_  3
#define IC_ 16

// tiny scratch: attention matrices after softmax + A  [N, S, V, V]
__device__ float g_att[N_ * S_ * V_ * V_];

// ---- packed f32x2 helpers ------------------------------------------------
__device__ __forceinline__ unsigned long long pk2(float lo, float hi) {
    unsigned long long r;
    asm("mov.b64 %0, {%1, %2};" : "=l"(r) : "f"(lo), "f"(hi));
    return r;
}
__device__ __forceinline__ void ffma2(unsigned long long& acc,
                                      unsigned long long a,
                                      unsigned long long b) {
    asm("fma.rn.f32x2 %0, %1, %2, %0;" : "+l"(acc) : "l"(a), "l"(b));
}
__device__ __forceinline__ float2 upk(unsigned long long p) {
    float2 f;
    asm("mov.b64 {%0, %1}, %2;" : "=f"(f.x), "=f"(f.y) : "l"(p));
    return f;
}

// ---------------------------------------------------------------------------
// Kernel A: per (n, s) compute att[v][w] = softmax_v( (1/(IC*T)) * sum_{i,t}
//   fa[i,t,v] * fb[i,t,w] ) + (A_base + PA)[s,v,w]
// ---------------------------------------------------------------------------
__global__ __launch_bounds__(256, 3) void attn_kernel(
    const float* __restrict__ x, const float* __restrict__ A_base,
    const float* __restrict__ PA, const float* __restrict__ Wa,
    const float* __restrict__ ba, const float* __restrict__ Wb,
    const float* __restrict__ bb)
{
    extern __shared__ float smem[];
    float* sWaT = smem;               // [64][16]  (c-major, i inner)
    float* sWbT = sWaT + 1024;        // [64][16]
    float* sX   = sWbT + 1024;        // [64][128]
    float* sfa  = sX + 8192;          // [16][128] (i rows)
    float* sfb  = sfa + 2048;         // [16][128]

    __shared__ float satt[256];
    __shared__ float sbias[32];
    __shared__ float colmax[16], colinv[16];
    __shared__ float spart[4 * 256];  // gram partials per k-group

    const int tid = threadIdx.x;
    const int n = blockIdx.x / S_;
    const int s = blockIdx.x % S_;

    for (int idx = tid; idx < IC_ * C_; idx += 256) {
        int i = idx >> 6, c = idx & 63;
        sWaT[c * 16 + i] = Wa[(s * IC_ + i) * C_ + c];
        sWbT[c * 16 + i] = Wb[(s * IC_ + i) * C_ + c];
    }
    if (tid < 16)      sbias[tid] = ba[s * 16 + tid];
    else if (tid < 32) sbias[tid] = bb[s * 16 + (tid - 16)];
    __syncthreads();

    const float* xn = x + (size_t)n * (C_ * T_ * V_);

    // fa/fb roles
    const int j = tid & 127;       // column within chunk (tt*16 + v)
    const int g = tid >> 7;        // 0 -> fa, 1 -> fb
    const float* WT = g ? sWbT : sWaT;
    float* F = g ? sfb : sfa;
    unsigned long long bias2[8];
    #pragma unroll
    for (int q = 0; q < 8; q++)
        bias2[q] = pk2(sbias[g * 16 + 2 * q], sbias[g * 16 + 2 * q + 1]);

    // gram roles: kg = k-group (of the 128 (i,tt) terms), v row, wp = w-quad
    const int kg = tid >> 6;
    const int v4 = (tid & 63) >> 2;
    const int wp = tid & 3;
    unsigned long long gacc[2];
    gacc[0] = 0ull; gacc[1] = 0ull;

    for (int t0 = 0; t0 < T_; t0 += 8) {
        for (int idx = tid; idx < 64 * 32; idx += 256) {
            int c = idx >> 5, q = idx & 31;
            reinterpret_cast<float4*>(sX + c * 128)[q] =
                reinterpret_cast<const float4*>(xn + (size_t)c * (T_ * V_) + t0 * V_)[q];
        }
        __syncthreads();

        // fa/fb chunk with packed fma: acc pairs over i
        {
            unsigned long long acc2[8];
            #pragma unroll
            for (int q = 0; q < 8; q++) acc2[q] = bias2[q];
            #pragma unroll 4
            for (int c = 0; c < 64; c++) {
                float xv = sX[c * 128 + j];
                unsigned long long xd = pk2(xv, xv);
                const ulonglong2* w2 = reinterpret_cast<const ulonglong2*>(WT + c * 16);
                ulonglong2 p0 = w2[0];
                ulonglong2 p1 = w2[1];
                ffma2(acc2[0], xd, p0.x);
                ffma2(acc2[1], xd, p0.y);
                ffma2(acc2[2], xd, p1.x);
                ffma2(acc2[3], xd, p1.y);
                ulonglong2 p2 = w2[2];
                ulonglong2 p3 = w2[3];
                ffma2(acc2[4], xd, p2.x);
                ffma2(acc2[5], xd, p2.y);
                ffma2(acc2[6], xd, p3.x);
                ffma2(acc2[7], xd, p3.y);
            }
            #pragma unroll
            for (int q = 0; q < 8; q++) {
                float2 f = upk(acc2[q]);
                F[(2 * q) * 128 + j]     = f.x;
                F[(2 * q + 1) * 128 + j] = f.y;
            }
        }
        __syncthreads();

        // gram: (i,tt) flattens to m with offset 16*m; this thread does
        // m = kg*32 .. kg*32+31
        {
            const float* pa = sfa + kg * 512 + v4;
            const float* pb = sfb + kg * 512 + wp * 4;
            #pragma unroll 8
            for (int u = 0; u < 32; u++) {
                float fav = pa[u * 16];
                unsigned long long fd = pk2(fav, fav);
                ulonglong2 fbp = *reinterpret_cast<const ulonglong2*>(pb + u * 16);
                ffma2(gacc[0], fd, fbp.x);
                ffma2(gacc[1], fd, fbp.y);
            }
        }
        __syncthreads();
    }

    // reduce gram partials
    {
        float2 g0 = upk(gacc[0]);
        float2 g1 = upk(gacc[1]);
        float* p = spart + kg * 256 + v4 * 16 + wp * 4;
        p[0] = g0.x; p[1] = g0.y; p[2] = g1.x; p[3] = g1.y;
    }
    __syncthreads();

    const int v = tid >> 4;
    const int w = tid & 15;
    float attacc = (spart[tid] + spart[256 + tid] + spart[512 + tid] +
                    spart[768 + tid]) * (1.0f / (float)(IC_ * T_));
    satt[tid] = attacc;
    __syncthreads();

    if (tid < 16) {
        float m = -1e30f;
        #pragma unroll
        for (int vv = 0; vv < 16; vv++) m = fmaxf(m, satt[vv * 16 + tid]);
        float ssum = 0.f;
        #pragma unroll
        for (int vv = 0; vv < 16; vv++) ssum += __expf(satt[vv * 16 + tid] - m);
        colmax[tid] = m;
        colinv[tid] = 1.0f / ssum;
    }
    __syncthreads();

    float r = __expf(attacc - colmax[w]) * colinv[w]
            + A_base[(s * 16 + v) * 16 + w] + PA[(s * 16 + v) * 16 + w];
    g_att[((n * 3 + s) * 16 + v) * 16 + w] = r;
}

// ---------------------------------------------------------------------------
// Kernel B: per (n, 8-t tile), s-sequential block GEMM:
//   stage1: Tmp_s[c][tw] = sum_v x[c][tw(t),v] * att_s[v][w]  (tw = t*16+w)
//   stage2: acc[o][tw]  += sum_c Wd_s[o][c] * Tmp_s[c][tw]    (reg 4o x 8tw)
//   epilogue: y=(acc+bds)*scl+bet staged to smem, + residual, float4 store
// ---------------------------------------------------------------------------
__global__ __launch_bounds__(256, 2) void out_kernel(
    const float* __restrict__ x, const float* __restrict__ Wd,
    const float* __restrict__ bd, const float* __restrict__ gamma,
    const float* __restrict__ beta, float* __restrict__ out)
{
    extern __shared__ float smem[];
    float* sWd  = smem;                // 2 x [64][68]  (c rows, o inner, padded)
    float* sAtt = sWd + 2 * 64 * 68;   // [3][16][16]
    float* sX   = sAtt + 768;          // [64][128]
    float* sTmp = sX + 8192;           // [64][128]

    const int tid = threadIdx.x;
    const int n  = blockIdx.y;
    const int t0 = blockIdx.x * 8;

    // preamble loads: att, x tile, Wd[0] -> buf0
    for (int idx = tid; idx < 768; idx += 256)
        sAtt[idx] = g_att[n * 768 + idx];
    for (int idx = tid; idx < 64 * 32; idx += 256) {
        int c = idx >> 5, q = idx & 31;
        reinterpret_cast<float4*>(sX + c * 128)[q] =
            reinterpret_cast<const float4*>(x + (size_t)(n * 64 + c) * (T_ * V_) + t0 * V_)[q];
    }
    for (int idx = tid; idx < C_ * C_; idx += 256) {
        int o = idx >> 6, c = idx & 63;
        sWd[c * 68 + o] = Wd[idx];     // s = 0
    }

    // epilogue constants: thread owns o = og*4..+3, tw = twg*8..+7
    const int og  = tid >> 4;
    const int twg = tid & 15;
    float bds[4], scl[4], bet[4];
    const float bn_inv = rsqrtf(1.0f + 1e-5f);
    #pragma unroll
    for (int jj = 0; jj < 4; jj++) {
        int o = og * 4 + jj;
        bds[jj] = bd[o] + bd[64 + o] + bd[128 + o];
        scl[jj] = gamma[o] * bn_inv;
        bet[jj] = beta[o];
    }
    __syncthreads();

    // stage1 roles
    const int c1 = tid >> 2;
    const int wg = tid & 3;

    unsigned long long acc2[16];       // [o 0..3][pair 0..3] over tw pairs
    #pragma unroll
    for (int q = 0; q < 16; q++) acc2[q] = 0ull;

    #pragma unroll
    for (int s = 0; s < S_; s++) {
        float* bufWd = sWd + (s & 1) * 4352;

        // ---- stage1: Tmp_s[c1][tt*16+wg*4..+3] for tt=0..7
        const float* attBase = sAtt + s * 256 + wg * 4;
        #pragma unroll
        for (int tt = 0; tt < 8; tt++) {
            const float4* xp = reinterpret_cast<const float4*>(sX + c1 * 128 + tt * 16);
            float xr[16];
            #pragma unroll
            for (int q = 0; q < 4; q++) {
                float4 xx = xp[q];
                xr[q * 4 + 0] = xx.x; xr[q * 4 + 1] = xx.y;
                xr[q * 4 + 2] = xx.z; xr[q * 4 + 3] = xx.w;
            }
            unsigned long long a0 = 0ull, a1 = 0ull;
            #pragma unroll
            for (int vv = 0; vv < 16; vv++) {
                unsigned long long xd = pk2(xr[vv], xr[vv]);
                ulonglong2 ap = *reinterpret_cast<const ulonglong2*>(attBase + vv * 16);
                ffma2(a0, xd, ap.x);
                ffma2(a1, xd, ap.y);
            }
            float2 f0 = upk(a0), f1 = upk(a1);
            *reinterpret_cast<float4*>(sTmp + c1 * 128 + tt * 16 + wg * 4) =
                make_float4(f0.x, f0.y, f1.x, f1.y);
        }
        __syncthreads();

        // ---- prefetch Wd[s+1] (global -> regs) while stage2 runs
        float4 pf[4];
        if (s < 2) {
            const float* src = Wd + (size_t)(s + 1) * 4096;
            #pragma unroll
            for (int q = 0; q < 4; q++) {
                int f = tid * 4 + q;          // float4 id: o = f>>4, c4 = f&15
                pf[q] = reinterpret_cast<const float4*>(src)[f];
            }
        }

        // ---- stage2: acc += Wd_s @ Tmp_s
        const float* tvBase = sTmp + twg * 8;
        const float* wdBase = bufWd + og * 4;
        #pragma unroll 4
        for (int c = 0; c < 64; c++) {
            float4 wd4 = *reinterpret_cast<const float4*>(wdBase + c * 68);
            const ulonglong2* tv2 = reinterpret_cast<const ulonglong2*>(tvBase + c * 128);
            ulonglong2 t01 = tv2[0];
            ulonglong2 t23 = tv2[1];
            unsigned long long d0 = pk2(wd4.x, wd4.x);
            ffma2(acc2[0], d0, t01.x); ffma2(acc2[1], d0, t01.y);
            ffma2(acc2[2], d0, t23.x); ffma2(acc2[3], d0, t23.y);
            unsigned long long d1 = pk2(wd4.y, wd4.y);
            ffma2(acc2[4], d1, t01.x); ffma2(acc2[5], d1, t01.y);
            ffma2(acc2[6], d1, t23.x); ffma2(acc2[7], d1, t23.y);
            unsigned long long d2 = pk2(wd4.z, wd4.z);
            ffma2(acc2[8],  d2, t01.x); ffma2(acc2[9],  d2, t01.y);
            ffma2(acc2[10], d2, t23.x); ffma2(acc2[11], d2, t23.y);
            unsigned long long d3 = pk2(wd4.w, wd4.w);
            ffma2(acc2[12], d3, t01.x); ffma2(acc2[13], d3, t01.y);
            ffma2(acc2[14], d3, t23.x); ffma2(acc2[15], d3, t23.y);
        }

        // ---- store prefetched Wd[s+1] into other buffer
        if (s < 2) {
            float* nb = sWd + ((s + 1) & 1) * 4352;
            #pragma unroll
            for (int q = 0; q < 4; q++) {
                int f = tid * 4 + q;
                int o = f >> 4, c4 = f & 15;
                nb[(c4 * 4 + 0) * 68 + o] = pf[q].x;
                nb[(c4 * 4 + 1) * 68 + o] = pf[q].y;
                nb[(c4 * 4 + 2) * 68 + o] = pf[q].z;
                nb[(c4 * 4 + 3) * 68 + o] = pf[q].w;
            }
        }
        __syncthreads();   // protects sTmp overwrite + publishes Wd[s+1]
    }

    // ---- epilogue: scale/bias into sTmp (reuse), then coalesced store
    #pragma unroll
    for (int o = 0; o < 4; o++) {
        float* dst = sTmp + (og * 4 + o) * 128 + twg * 8;
        #pragma unroll
        for (int p = 0; p < 4; p++) {
            float2 f = upk(acc2[o * 4 + p]);
            dst[p * 2 + 0] = (f.x + bds[o]) * scl[o] + bet[o];
            dst[p * 2 + 1] = (f.y + bds[o]) * scl[o] + bet[o];
        }
    }
    __syncthreads();

    for (int idx = tid; idx < 64 * 32; idx += 256) {
        int c = idx >> 5, q = idx & 31;
        float4 yv = reinterpret_cast<const float4*>(sTmp + c * 128)[q];
        float4 xv = reinterpret_cast<const float4*>(sX + c * 128)[q];
        yv.x += xv.x; yv.y += xv.y; yv.z += xv.z; yv.w += xv.w;
        reinterpret_cast<float4*>(out + (size_t)(n * 64 + c) * (T_ * V_) + t0 * V_)[q] = yv;
    }
}

extern "C" void kernel_launch(void* const* d_in, const int* in_sizes, int n_in,
                              void* d_out, int out_size)
{
    const float* x      = (const float*)d_in[0];
    const float* A_base = (const float*)d_in[1];
    const float* PA     = (const float*)d_in[2];
    const float* Wa     = (const float*)d_in[3];
    const float* ba     = (const float*)d_in[4];
    const float* Wb     = (const float*)d_in[5];
    const float* bb     = (const float*)d_in[6];
    const float* Wd     = (const float*)d_in[7];
    const float* bd     = (const float*)d_in[8];
    const float* gamma  = (const float*)d_in[9];
    const float* beta   = (const float*)d_in[10];
    float* out = (float*)d_out;

    const int smemA = (1024 * 2 + 8192 + 2048 * 2) * sizeof(float);            // 57344 B
    const int smemB = (2 * 64 * 68 + 768 + 8192 + 8192) * sizeof(float);       // 103424 B

    cudaFuncSetAttribute(attn_kernel, cudaFuncAttributeMaxDynamicSharedMemorySize, smemA);
    cudaFuncSetAttribute(out_kernel,  cudaFuncAttributeMaxDynamicSharedMemorySize, smemB);

    attn_kernel<<<N_ * S_, 256, smemA>>>(x, A_base, PA, Wa, ba, Wb, bb);
    out_kernel<<<dim3(T_ / 8, N_), 256, smemB>>>(x, Wd, bd, gamma, beta, out);
}

// round 5
// speedup vs baseline: 1.7444x; 1.3264x over previous
#include <cuda_runtime.h>
#include <cstdint>

#define N_  128
#define C_  64
#define T_  288
#define V_  16
#define S_  3
#define IC_ 16

// tiny scratch: attention matrices after softmax + A  [N, S, V, V]
__device__ float g_att[N_ * S_ * V_ * V_];

// ---- packed f32x2 helpers ------------------------------------------------
__device__ __forceinline__ unsigned long long pk2(float lo, float hi) {
    unsigned long long r;
    asm("mov.b64 %0, {%1, %2};" : "=l"(r) : "f"(lo), "f"(hi));
    return r;
}
__device__ __forceinline__ void ffma2(unsigned long long& acc,
                                      unsigned long long a,
                                      unsigned long long b) {
    asm("fma.rn.f32x2 %0, %1, %2, %0;" : "+l"(acc) : "l"(a), "l"(b));
}
__device__ __forceinline__ float2 upk(unsigned long long p) {
    float2 f;
    asm("mov.b64 {%0, %1}, %2;" : "=f"(f.x), "=f"(f.y) : "l"(p));
    return f;
}
__device__ __forceinline__ uint32_t f2tf32(float f) {
    uint32_t r;
    asm("cvt.rna.tf32.f32 %0, %1;" : "=r"(r) : "f"(f));
    return r;
}
__device__ __forceinline__ void mma_tf32(float& d0, float& d1, float& d2, float& d3,
                                         uint32_t a0, uint32_t a1, uint32_t a2, uint32_t a3,
                                         uint32_t b0, uint32_t b1) {
    asm volatile("mma.sync.aligned.m16n8k8.row.col.f32.tf32.tf32.f32 "
                 "{%0,%1,%2,%3}, {%4,%5,%6,%7}, {%8,%9}, {%0,%1,%2,%3};"
                 : "+f"(d0), "+f"(d1), "+f"(d2), "+f"(d3)
                 : "r"(a0), "r"(a1), "r"(a2), "r"(a3), "r"(b0), "r"(b1));
}

// ---------------------------------------------------------------------------
// Kernel A: unchanged (R3, passing)
// ---------------------------------------------------------------------------
__global__ __launch_bounds__(256, 3) void attn_kernel(
    const float* __restrict__ x, const float* __restrict__ A_base,
    const float* __restrict__ PA, const float* __restrict__ Wa,
    const float* __restrict__ ba, const float* __restrict__ Wb,
    const float* __restrict__ bb)
{
    extern __shared__ float smemf[];
    float* sWaT = smemf;
    float* sWbT = sWaT + 1024;
    float* sX   = sWbT + 1024;
    float* sfa  = sX + 8192;
    float* sfb  = sfa + 2048;

    __shared__ float satt[256];
    __shared__ float sbias[32];
    __shared__ float colmax[16], colinv[16];
    __shared__ float spart[4 * 256];

    const int tid = threadIdx.x;
    const int n = blockIdx.x / S_;
    const int s = blockIdx.x % S_;

    for (int idx = tid; idx < IC_ * C_; idx += 256) {
        int i = idx >> 6, c = idx & 63;
        sWaT[c * 16 + i] = Wa[(s * IC_ + i) * C_ + c];
        sWbT[c * 16 + i] = Wb[(s * IC_ + i) * C_ + c];
    }
    if (tid < 16)      sbias[tid] = ba[s * 16 + tid];
    else if (tid < 32) sbias[tid] = bb[s * 16 + (tid - 16)];
    __syncthreads();

    const float* xn = x + (size_t)n * (C_ * T_ * V_);

    const int j = tid & 127;
    const int g = tid >> 7;
    const float* WT = g ? sWbT : sWaT;
    float* F = g ? sfb : sfa;
    unsigned long long bias2[8];
    #pragma unroll
    for (int q = 0; q < 8; q++)
        bias2[q] = pk2(sbias[g * 16 + 2 * q], sbias[g * 16 + 2 * q + 1]);

    const int kg = tid >> 6;
    const int v4 = (tid & 63) >> 2;
    const int wp = tid & 3;
    unsigned long long gacc[2];
    gacc[0] = 0ull; gacc[1] = 0ull;

    for (int t0 = 0; t0 < T_; t0 += 8) {
        for (int idx = tid; idx < 64 * 32; idx += 256) {
            int c = idx >> 5, q = idx & 31;
            reinterpret_cast<float4*>(sX + c * 128)[q] =
                reinterpret_cast<const float4*>(xn + (size_t)c * (T_ * V_) + t0 * V_)[q];
        }
        __syncthreads();

        {
            unsigned long long acc2[8];
            #pragma unroll
            for (int q = 0; q < 8; q++) acc2[q] = bias2[q];
            #pragma unroll 4
            for (int c = 0; c < 64; c++) {
                float xv = sX[c * 128 + j];
                unsigned long long xd = pk2(xv, xv);
                const ulonglong2* w2 = reinterpret_cast<const ulonglong2*>(WT + c * 16);
                ulonglong2 p0 = w2[0];
                ulonglong2 p1 = w2[1];
                ffma2(acc2[0], xd, p0.x);
                ffma2(acc2[1], xd, p0.y);
                ffma2(acc2[2], xd, p1.x);
                ffma2(acc2[3], xd, p1.y);
                ulonglong2 p2 = w2[2];
                ulonglong2 p3 = w2[3];
                ffma2(acc2[4], xd, p2.x);
                ffma2(acc2[5], xd, p2.y);
                ffma2(acc2[6], xd, p3.x);
                ffma2(acc2[7], xd, p3.y);
            }
            #pragma unroll
            for (int q = 0; q < 8; q++) {
                float2 f = upk(acc2[q]);
                F[(2 * q) * 128 + j]     = f.x;
                F[(2 * q + 1) * 128 + j] = f.y;
            }
        }
        __syncthreads();

        {
            const float* pa = sfa + kg * 512 + v4;
            const float* pb = sfb + kg * 512 + wp * 4;
            #pragma unroll 8
            for (int u = 0; u < 32; u++) {
                float fav = pa[u * 16];
                unsigned long long fd = pk2(fav, fav);
                ulonglong2 fbp = *reinterpret_cast<const ulonglong2*>(pb + u * 16);
                ffma2(gacc[0], fd, fbp.x);
                ffma2(gacc[1], fd, fbp.y);
            }
        }
        __syncthreads();
    }

    {
        float2 g0 = upk(gacc[0]);
        float2 g1 = upk(gacc[1]);
        float* p = spart + kg * 256 + v4 * 16 + wp * 4;
        p[0] = g0.x; p[1] = g0.y; p[2] = g1.x; p[3] = g1.y;
    }
    __syncthreads();

    const int v = tid >> 4;
    const int w = tid & 15;
    float attacc = (spart[tid] + spart[256 + tid] + spart[512 + tid] +
                    spart[768 + tid]) * (1.0f / (float)(IC_ * T_));
    satt[tid] = attacc;
    __syncthreads();

    if (tid < 16) {
        float m = -1e30f;
        #pragma unroll
        for (int vv = 0; vv < 16; vv++) m = fmaxf(m, satt[vv * 16 + tid]);
        float ssum = 0.f;
        #pragma unroll
        for (int vv = 0; vv < 16; vv++) ssum += __expf(satt[vv * 16 + tid] - m);
        colmax[tid] = m;
        colinv[tid] = 1.0f / ssum;
    }
    __syncthreads();

    float r = __expf(attacc - colmax[w]) * colinv[w]
            + A_base[(s * 16 + v) * 16 + w] + PA[(s * 16 + v) * 16 + w];
    g_att[((n * 3 + s) * 16 + v) * 16 + w] = r;
}

// ---------------------------------------------------------------------------
// Kernel B (mma.sync tf32): per (n, 8-t tile):
//   stage1 (FFMA2): Z_s[tw=128][c=64] in tf32, smem pitch 76 (u32)
//   stage2 (mma.sync m16n8k8): D[128tw,64o] += Z_s @ W_s[c][o] (pitch 72)
//   epilogue: BN+bias, +residual from sX, coalesced store
// smem (bytes): sZ 38912 @0 | sW 2x18432 @38912 | sX 32768 @75776 | att @108544
// ---------------------------------------------------------------------------
#define ZP 76
#define WP 72
__global__ __launch_bounds__(256, 2) void out_kernel(
    const float* __restrict__ x, const float* __restrict__ Wd,
    const float* __restrict__ bd, const float* __restrict__ gamma,
    const float* __restrict__ beta, float* __restrict__ out)
{
    extern __shared__ char smem[];
    uint32_t* sZ  = (uint32_t*)(smem);                 // [128][ZP] tf32
    float*    sO  = (float*)(smem);                    // epilogue reuse [64][128]
    uint32_t* sW0 = (uint32_t*)(smem + 38912);         // [64][WP] tf32
    uint32_t* sW1 = (uint32_t*)(smem + 57344);
    float*    sX  = (float*)(smem + 75776);            // [64][128]
    float*    sAtt= (float*)(smem + 108544);           // [3][16][16]

    __shared__ float sBN[3 * 64];

    const int tid  = threadIdx.x;
    const int wid  = tid >> 5;
    const int lane = tid & 31;
    const int n  = blockIdx.y;
    const int t0 = blockIdx.x * 8;

    // preamble: att, x tile, W_0, BN constants
    for (int idx = tid; idx < 768; idx += 256)
        sAtt[idx] = g_att[n * 768 + idx];
    for (int idx = tid; idx < 64 * 32; idx += 256) {
        int c = idx >> 5, q = idx & 31;
        reinterpret_cast<float4*>(sX + c * 128)[q] =
            reinterpret_cast<const float4*>(x + (size_t)(n * 64 + c) * (T_ * V_) + t0 * V_)[q];
    }
    #pragma unroll
    for (int q = 0; q < 4; q++) {
        int i4 = tid + q * 256;            // o = i4>>4, c-quad = i4&15
        int o = i4 >> 4, c4 = i4 & 15;
        float4 wv = reinterpret_cast<const float4*>(Wd)[i4];
        sW0[(c4 * 4 + 0) * WP + o] = f2tf32(wv.x);
        sW0[(c4 * 4 + 1) * WP + o] = f2tf32(wv.y);
        sW0[(c4 * 4 + 2) * WP + o] = f2tf32(wv.z);
        sW0[(c4 * 4 + 3) * WP + o] = f2tf32(wv.w);
    }
    if (tid < 64) {
        int o = tid;
        sBN[o]       = bd[o] + bd[64 + o] + bd[128 + o];
        sBN[64 + o]  = gamma[o] * rsqrtf(1.0f + 1e-5f);
        sBN[128 + o] = beta[o];
    }
    __syncthreads();

    // stage1 roles
    const int c1 = tid >> 2;
    const int wg = tid & 3;

    // mma roles
    const int m0   = wid * 16;
    const int rA0  = m0 + (lane >> 2);
    const int kq   = lane & 3;
    const int ncol = lane >> 2;

    float acc[8][4];
    #pragma unroll
    for (int nf = 0; nf < 8; nf++) {
        acc[nf][0] = 0.f; acc[nf][1] = 0.f; acc[nf][2] = 0.f; acc[nf][3] = 0.f;
    }

    #pragma unroll
    for (int s = 0; s < S_; s++) {
        uint32_t* sWcur = (s & 1) ? sW1 : sW0;

        // ---- stage1: Z_s[tw][c1] tf32
        ulonglong2 ar[16];
        #pragma unroll
        for (int v = 0; v < 16; v++)
            ar[v] = *reinterpret_cast<const ulonglong2*>(sAtt + s * 256 + v * 16 + wg * 4);

        #pragma unroll
        for (int tt = 0; tt < 8; tt++) {
            const float4* xp = reinterpret_cast<const float4*>(sX + c1 * 128 + tt * 16);
            float xr[16];
            #pragma unroll
            for (int q = 0; q < 4; q++) {
                float4 xx = xp[q];
                xr[q * 4 + 0] = xx.x; xr[q * 4 + 1] = xx.y;
                xr[q * 4 + 2] = xx.z; xr[q * 4 + 3] = xx.w;
            }
            unsigned long long a0 = 0ull, a1 = 0ull;
            #pragma unroll
            for (int v = 0; v < 16; v++) {
                unsigned long long xd = pk2(xr[v], xr[v]);
                ffma2(a0, xd, ar[v].x);
                ffma2(a1, xd, ar[v].y);
            }
            float2 f0 = upk(a0), f1 = upk(a1);
            const int twb = tt * 16 + wg * 4;
            sZ[(twb + 0) * ZP + c1] = f2tf32(f0.x);
            sZ[(twb + 1) * ZP + c1] = f2tf32(f0.y);
            sZ[(twb + 2) * ZP + c1] = f2tf32(f1.x);
            sZ[(twb + 3) * ZP + c1] = f2tf32(f1.y);
        }

        // prefetch W_{s+1} into other buffer while this stage used regs
        if (s < 2) {
            uint32_t* sWn = ((s + 1) & 1) ? sW1 : sW0;
            const float4* src = reinterpret_cast<const float4*>(Wd + (size_t)(s + 1) * 4096);
            #pragma unroll
            for (int q = 0; q < 4; q++) {
                int i4 = tid + q * 256;
                int o = i4 >> 4, c4 = i4 & 15;
                float4 wv = src[i4];
                sWn[(c4 * 4 + 0) * WP + o] = f2tf32(wv.x);
                sWn[(c4 * 4 + 1) * WP + o] = f2tf32(wv.y);
                sWn[(c4 * 4 + 2) * WP + o] = f2tf32(wv.z);
                sWn[(c4 * 4 + 3) * WP + o] = f2tf32(wv.w);
            }
        }
        __syncthreads();   // Z_s + W visible

        // ---- stage2: 8 k-steps of m16n8k8 over c
        #pragma unroll
        for (int ks = 0; ks < 8; ks++) {
            const int k0 = ks * 8;
            uint32_t a0 = sZ[rA0 * ZP + k0 + kq];
            uint32_t a1 = sZ[(rA0 + 8) * ZP + k0 + kq];
            uint32_t a2 = sZ[rA0 * ZP + k0 + 4 + kq];
            uint32_t a3 = sZ[(rA0 + 8) * ZP + k0 + 4 + kq];
            const uint32_t* bp0 = sWcur + (k0 + kq) * WP + ncol;
            const uint32_t* bp1 = sWcur + (k0 + 4 + kq) * WP + ncol;
            #pragma unroll
            for (int nf = 0; nf < 8; nf++) {
                uint32_t b0 = bp0[nf * 8];
                uint32_t b1 = bp1[nf * 8];
                mma_tf32(acc[nf][0], acc[nf][1], acc[nf][2], acc[nf][3],
                         a0, a1, a2, a3, b0, b1);
            }
        }
        __syncthreads();   // done reading Z_s before next stage1 overwrites
    }

    // ---- epilogue: BN+bias into sO[o][tw] (reuses sZ region)
    {
        const int r0 = m0 + (lane >> 2);
        #pragma unroll
        for (int nf = 0; nf < 8; nf++) {
            int o0 = nf * 8 + 2 * (lane & 3);
            float s0 = sBN[64 + o0],     b0v = sBN[o0],     z0 = sBN[128 + o0];
            float s1 = sBN[64 + o0 + 1], b1v = sBN[o0 + 1], z1 = sBN[128 + o0 + 1];
            sO[o0 * 128 + r0]           = (acc[nf][0] + b0v) * s0 + z0;
            sO[(o0 + 1) * 128 + r0]     = (acc[nf][1] + b1v) * s1 + z1;
            sO[o0 * 128 + r0 + 8]       = (acc[nf][2] + b0v) * s0 + z0;
            sO[(o0 + 1) * 128 + r0 + 8] = (acc[nf][3] + b1v) * s1 + z1;
        }
    }
    __syncthreads();

    for (int idx = tid; idx < 64 * 32; idx += 256) {
        int c = idx >> 5, q = idx & 31;
        float4 yv = reinterpret_cast<const float4*>(sO + c * 128)[q];
        float4 xv = reinterpret_cast<const float4*>(sX + c * 128)[q];
        yv.x += xv.x; yv.y += xv.y; yv.z += xv.z; yv.w += xv.w;
        reinterpret_cast<float4*>(out + (size_t)(n * 64 + c) * (T_ * V_) + t0 * V_)[q] = yv;
    }
}

extern "C" void kernel_launch(void* const* d_in, const int* in_sizes, int n_in,
                              void* d_out, int out_size)
{
    const float* x      = (const float*)d_in[0];
    const float* A_base = (const float*)d_in[1];
    const float* PA     = (const float*)d_in[2];
    const float* Wa     = (const float*)d_in[3];
    const float* ba     = (const float*)d_in[4];
    const float* Wb     = (const float*)d_in[5];
    const float* bb     = (const float*)d_in[6];
    const float* Wd     = (const float*)d_in[7];
    const float* bd     = (const float*)d_in[8];
    const float* gamma  = (const float*)d_in[9];
    const float* beta   = (const float*)d_in[10];
    float* out = (float*)d_out;

    const int smemA = (1024 * 2 + 8192 + 2048 * 2) * sizeof(float);   // 57344 B
    const int smemB = 111616;                                         // bytes

    cudaFuncSetAttribute(attn_kernel, cudaFuncAttributeMaxDynamicSharedMemorySize, smemA);
    cudaFuncSetAttribute(out_kernel,  cudaFuncAttributeMaxDynamicSharedMemorySize, smemB);

    attn_kernel<<<N_ * S_, 256, smemA>>>(x, A_base, PA, Wa, ba, Wb, bb);
    out_kernel<<<dim3(T_ / 8, N_), 256, smemB>>>(x, Wd, bd, gamma, beta, out);
}

// round 6
// speedup vs baseline: 1.8800x; 1.0777x over previous
#include <cuda_runtime.h>
#include <cstdint>

#define N_  128
#define C_  64
#define T_  288
#define V_  16
#define S_  3
#define IC_ 16

// tiny scratch: attention matrices after softmax + A  [N, S, V, V]
__device__ float g_att[N_ * S_ * V_ * V_];

// ---- packed f32x2 helpers ------------------------------------------------
__device__ __forceinline__ unsigned long long pk2(float lo, float hi) {
    unsigned long long r;
    asm("mov.b64 %0, {%1, %2};" : "=l"(r) : "f"(lo), "f"(hi));
    return r;
}
__device__ __forceinline__ void ffma2(unsigned long long& acc,
                                      unsigned long long a,
                                      unsigned long long b) {
    asm("fma.rn.f32x2 %0, %1, %2, %0;" : "+l"(acc) : "l"(a), "l"(b));
}
__device__ __forceinline__ float2 upk(unsigned long long p) {
    float2 f;
    asm("mov.b64 {%0, %1}, %2;" : "=f"(f.x), "=f"(f.y) : "l"(p));
    return f;
}
__device__ __forceinline__ uint32_t f2tf32(float f) {
    uint32_t r;
    asm("cvt.rna.tf32.f32 %0, %1;" : "=r"(r) : "f"(f));
    return r;
}
__device__ __forceinline__ void mma_tf32(float& d0, float& d1, float& d2, float& d3,
                                         uint32_t a0, uint32_t a1, uint32_t a2, uint32_t a3,
                                         uint32_t b0, uint32_t b1) {
    asm volatile("mma.sync.aligned.m16n8k8.row.col.f32.tf32.tf32.f32 "
                 "{%0,%1,%2,%3}, {%4,%5,%6,%7}, {%8,%9}, {%0,%1,%2,%3};"
                 : "+f"(d0), "+f"(d1), "+f"(d2), "+f"(d3)
                 : "r"(a0), "r"(a1), "r"(a2), "r"(a3), "r"(b0), "r"(b1));
}

// ---------------------------------------------------------------------------
// Kernel A: per (n, s): att = softmax(gram/(IC*T)) + A_base + PA
// 2-chunk version: 16 t's per x stage; each thread owns 2 columns so each
// broadcast W load feeds 2 columns of FFMA2.
// ---------------------------------------------------------------------------
__global__ __launch_bounds__(256, 2) void attn_kernel(
    const float* __restrict__ x, const float* __restrict__ A_base,
    const float* __restrict__ PA, const float* __restrict__ Wa,
    const float* __restrict__ ba, const float* __restrict__ Wb,
    const float* __restrict__ bb)
{
    extern __shared__ float smemf[];
    float* sWaT = smemf;               // [64][16]
    float* sWbT = sWaT + 1024;         // [64][16]
    float* sX   = sWbT + 1024;         // [64][256]
    float* sfa  = sX + 16384;          // [16][256]
    float* sfb  = sfa + 4096;          // [16][256]

    __shared__ float satt[256];
    __shared__ float sbias[32];
    __shared__ float colmax[16], colinv[16];
    __shared__ float spart[4 * 256];

    const int tid = threadIdx.x;
    const int n = blockIdx.x / S_;
    const int s = blockIdx.x % S_;

    for (int idx = tid; idx < IC_ * C_; idx += 256) {
        int i = idx >> 6, c = idx & 63;
        sWaT[c * 16 + i] = Wa[(s * IC_ + i) * C_ + c];
        sWbT[c * 16 + i] = Wb[(s * IC_ + i) * C_ + c];
    }
    if (tid < 16)      sbias[tid] = ba[s * 16 + tid];
    else if (tid < 32) sbias[tid] = bb[s * 16 + (tid - 16)];
    __syncthreads();

    const float* xn = x + (size_t)n * (C_ * T_ * V_);

    const int j0 = tid & 127;          // first column; second is j0+128
    const int g = tid >> 7;            // 0 -> fa, 1 -> fb
    const float* WT = g ? sWbT : sWaT;
    float* F = g ? sfb : sfa;
    unsigned long long bias2[8];
    #pragma unroll
    for (int q = 0; q < 8; q++)
        bias2[q] = pk2(sbias[g * 16 + 2 * q], sbias[g * 16 + 2 * q + 1]);

    const int kg = tid >> 6;           // gram k-group (64 of 256 (i,tt) terms)
    const int v4 = (tid & 63) >> 2;
    const int wp = tid & 3;
    unsigned long long gacc[2];
    gacc[0] = 0ull; gacc[1] = 0ull;

    for (int t0 = 0; t0 < T_; t0 += 16) {
        // x[n, :, t0:t0+16, :] -> sX: 64 rows x 256 floats
        for (int idx = tid; idx < 64 * 64; idx += 256) {
            int c = idx >> 6, q = idx & 63;
            reinterpret_cast<float4*>(sX + c * 256)[q] =
                reinterpret_cast<const float4*>(xn + (size_t)c * (T_ * V_) + t0 * V_)[q];
        }
        __syncthreads();

        // fa/fb: thread owns columns j0 and j0+128, all 16 i
        {
            unsigned long long acc0[8], acc1[8];
            #pragma unroll
            for (int q = 0; q < 8; q++) { acc0[q] = bias2[q]; acc1[q] = bias2[q]; }
            #pragma unroll 4
            for (int c = 0; c < 64; c++) {
                float xv0 = sX[c * 256 + j0];
                float xv1 = sX[c * 256 + j0 + 128];
                unsigned long long x0 = pk2(xv0, xv0);
                unsigned long long x1 = pk2(xv1, xv1);
                const ulonglong2* w2 = reinterpret_cast<const ulonglong2*>(WT + c * 16);
                ulonglong2 p0 = w2[0];
                ulonglong2 p1 = w2[1];
                ffma2(acc0[0], x0, p0.x); ffma2(acc1[0], x1, p0.x);
                ffma2(acc0[1], x0, p0.y); ffma2(acc1[1], x1, p0.y);
                ffma2(acc0[2], x0, p1.x); ffma2(acc1[2], x1, p1.x);
                ffma2(acc0[3], x0, p1.y); ffma2(acc1[3], x1, p1.y);
                ulonglong2 p2 = w2[2];
                ulonglong2 p3 = w2[3];
                ffma2(acc0[4], x0, p2.x); ffma2(acc1[4], x1, p2.x);
                ffma2(acc0[5], x0, p2.y); ffma2(acc1[5], x1, p2.y);
                ffma2(acc0[6], x0, p3.x); ffma2(acc1[6], x1, p3.x);
                ffma2(acc0[7], x0, p3.y); ffma2(acc1[7], x1, p3.y);
            }
            #pragma unroll
            for (int q = 0; q < 8; q++) {
                float2 f0 = upk(acc0[q]);
                float2 f1 = upk(acc1[q]);
                F[(2 * q) * 256 + j0]           = f0.x;
                F[(2 * q + 1) * 256 + j0]       = f0.y;
                F[(2 * q) * 256 + j0 + 128]     = f1.x;
                F[(2 * q + 1) * 256 + j0 + 128] = f1.y;
            }
        }
        __syncthreads();

        // gram: 256 (i,tt) terms, group kg owns 64
        {
            const float* pa = sfa + kg * 1024 + v4;
            const float* pb = sfb + kg * 1024 + wp * 4;
            #pragma unroll 8
            for (int u = 0; u < 64; u++) {
                float fav = pa[u * 16];
                unsigned long long fd = pk2(fav, fav);
                ulonglong2 fbp = *reinterpret_cast<const ulonglong2*>(pb + u * 16);
                ffma2(gacc[0], fd, fbp.x);
                ffma2(gacc[1], fd, fbp.y);
            }
        }
        __syncthreads();
    }

    {
        float2 g0 = upk(gacc[0]);
        float2 g1 = upk(gacc[1]);
        float* p = spart + kg * 256 + v4 * 16 + wp * 4;
        p[0] = g0.x; p[1] = g0.y; p[2] = g1.x; p[3] = g1.y;
    }
    __syncthreads();

    const int v = tid >> 4;
    const int w = tid & 15;
    float attacc = (spart[tid] + spart[256 + tid] + spart[512 + tid] +
                    spart[768 + tid]) * (1.0f / (float)(IC_ * T_));
    satt[tid] = attacc;
    __syncthreads();

    if (tid < 16) {
        float m = -1e30f;
        #pragma unroll
        for (int vv = 0; vv < 16; vv++) m = fmaxf(m, satt[vv * 16 + tid]);
        float ssum = 0.f;
        #pragma unroll
        for (int vv = 0; vv < 16; vv++) ssum += __expf(satt[vv * 16 + tid] - m);
        colmax[tid] = m;
        colinv[tid] = 1.0f / ssum;
    }
    __syncthreads();

    float r = __expf(attacc - colmax[w]) * colinv[w]
            + A_base[(s * 16 + v) * 16 + w] + PA[(s * 16 + v) * 16 + w];
    g_att[((n * 3 + s) * 16 + v) * 16 + w] = r;
}

// ---------------------------------------------------------------------------
// Kernel B (mma.sync tf32), fragment-native smem layouts:
//   Z [tw=128][k'] pitch 74, k interleaved (2*(k%4)+k/4 within 8-groups)
//     -> A fragments via 2x LDS.64, conflict-free stage1 STS
//   W [k=64][o'] pitch 68, o' = (o&7)*8 + o>>3
//     -> B fragments via 4x LDS.128 per k-step
// smem(B): sZ 37888 @0 | sW0 @37888 | sW1 @55296 | sX @72704 | att @105472
// ---------------------------------------------------------------------------
#define ZP2 74
#define WP2 68
__global__ __launch_bounds__(256, 2) void out_kernel(
    const float* __restrict__ x, const float* __restrict__ Wd,
    const float* __restrict__ bd, const float* __restrict__ gamma,
    const float* __restrict__ beta, float* __restrict__ out)
{
    extern __shared__ char smem[];
    uint32_t* sZ  = (uint32_t*)(smem);                 // [128][ZP2] tf32
    float*    sO  = (float*)(smem);                    // epilogue reuse [64][128]
    uint32_t* sW0 = (uint32_t*)(smem + 37888);         // [64][WP2] tf32
    uint32_t* sW1 = (uint32_t*)(smem + 55296);
    float*    sX  = (float*)(smem + 72704);            // [64][128]
    float*    sAtt= (float*)(smem + 105472);           // [3][16][16]

    __shared__ float sBN[3 * 64];

    const int tid  = threadIdx.x;
    const int wid  = tid >> 5;
    const int lane = tid & 31;
    const int n  = blockIdx.y;
    const int t0 = blockIdx.x * 8;

    // W-store roles: thread owns output channel o, k-block kb (16 c's)
    const int wo  = tid & 63;
    const int wkb = tid >> 6;
    const int wop = (wo & 7) * 8 + (wo >> 3);

    // preamble: att, x tile, W_0, BN constants
    for (int idx = tid; idx < 768; idx += 256)
        sAtt[idx] = g_att[n * 768 + idx];
    for (int idx = tid; idx < 64 * 32; idx += 256) {
        int c = idx >> 5, q = idx & 31;
        reinterpret_cast<float4*>(sX + c * 128)[q] =
            reinterpret_cast<const float4*>(x + (size_t)(n * 64 + c) * (T_ * V_) + t0 * V_)[q];
    }
    {
        const float4* src = reinterpret_cast<const float4*>(Wd + (size_t)wo * 64 + wkb * 16);
        #pragma unroll
        for (int q = 0; q < 4; q++) {
            float4 wv = src[q];
            int c = wkb * 16 + q * 4;
            sW0[(c + 0) * WP2 + wop] = f2tf32(wv.x);
            sW0[(c + 1) * WP2 + wop] = f2tf32(wv.y);
            sW0[(c + 2) * WP2 + wop] = f2tf32(wv.z);
            sW0[(c + 3) * WP2 + wop] = f2tf32(wv.w);
        }
    }
    if (tid < 64) {
        int o = tid;
        sBN[o]       = bd[o] + bd[64 + o] + bd[128 + o];
        sBN[64 + o]  = gamma[o] * rsqrtf(1.0f + 1e-5f);
        sBN[128 + o] = beta[o];
    }
    __syncthreads();

    // stage1 roles
    const int c1 = tid >> 2;
    const int wg = tid & 3;
    const int zc = (c1 & ~7) | (2 * (c1 & 3) + ((c1 >> 2) & 1));  // k-interleave

    // mma roles
    const int m0   = wid * 16;
    const int rA0  = m0 + (lane >> 2);
    const int kq   = lane & 3;
    const int ncol = lane >> 2;

    float acc[8][4];
    #pragma unroll
    for (int nf = 0; nf < 8; nf++) {
        acc[nf][0] = 0.f; acc[nf][1] = 0.f; acc[nf][2] = 0.f; acc[nf][3] = 0.f;
    }

    #pragma unroll
    for (int s = 0; s < S_; s++) {
        uint32_t* sWcur = (s & 1) ? sW1 : sW0;

        // ---- stage1: Z_s[tw][zc] tf32, conflict-free STS
        ulonglong2 ar[16];
        #pragma unroll
        for (int v = 0; v < 16; v++)
            ar[v] = *reinterpret_cast<const ulonglong2*>(sAtt + s * 256 + v * 16 + wg * 4);

        #pragma unroll
        for (int tt = 0; tt < 8; tt++) {
            const float4* xp = reinterpret_cast<const float4*>(sX + c1 * 128 + tt * 16);
            float xr[16];
            #pragma unroll
            for (int q = 0; q < 4; q++) {
                float4 xx = xp[q];
                xr[q * 4 + 0] = xx.x; xr[q * 4 + 1] = xx.y;
                xr[q * 4 + 2] = xx.z; xr[q * 4 + 3] = xx.w;
            }
            unsigned long long a0 = 0ull, a1 = 0ull;
            #pragma unroll
            for (int v = 0; v < 16; v++) {
                unsigned long long xd = pk2(xr[v], xr[v]);
                ffma2(a0, xd, ar[v].x);
                ffma2(a1, xd, ar[v].y);
            }
            float2 f0 = upk(a0), f1 = upk(a1);
            const int twb = tt * 16 + wg * 4;
            sZ[(twb + 0) * ZP2 + zc] = f2tf32(f0.x);
            sZ[(twb + 1) * ZP2 + zc] = f2tf32(f0.y);
            sZ[(twb + 2) * ZP2 + zc] = f2tf32(f1.x);
            sZ[(twb + 3) * ZP2 + zc] = f2tf32(f1.y);
        }

        // prefetch W_{s+1}
        if (s < 2) {
            uint32_t* sWn = ((s + 1) & 1) ? sW1 : sW0;
            const float4* src = reinterpret_cast<const float4*>(
                Wd + (size_t)(s + 1) * 4096 + (size_t)wo * 64 + wkb * 16);
            #pragma unroll
            for (int q = 0; q < 4; q++) {
                float4 wv = src[q];
                int c = wkb * 16 + q * 4;
                sWn[(c + 0) * WP2 + wop] = f2tf32(wv.x);
                sWn[(c + 1) * WP2 + wop] = f2tf32(wv.y);
                sWn[(c + 2) * WP2 + wop] = f2tf32(wv.z);
                sWn[(c + 3) * WP2 + wop] = f2tf32(wv.w);
            }
        }
        __syncthreads();   // Z_s + W visible

        // ---- stage2: 8 k-steps of m16n8k8; A via LDS.64, B via LDS.128
        #pragma unroll
        for (int ks = 0; ks < 8; ks++) {
            const int k0 = ks * 8;
            uint2 A02 = *reinterpret_cast<const uint2*>(sZ + rA0 * ZP2 + k0 + 2 * kq);
            uint2 A13 = *reinterpret_cast<const uint2*>(sZ + (rA0 + 8) * ZP2 + k0 + 2 * kq);
            const uint32_t* br0 = sWcur + (k0 + kq) * WP2 + ncol * 8;
            const uint32_t* br1 = sWcur + (k0 + 4 + kq) * WP2 + ncol * 8;
            uint4 b0lo = *reinterpret_cast<const uint4*>(br0);
            uint4 b0hi = *reinterpret_cast<const uint4*>(br0 + 4);
            uint4 b1lo = *reinterpret_cast<const uint4*>(br1);
            uint4 b1hi = *reinterpret_cast<const uint4*>(br1 + 4);
            uint32_t b0[8] = {b0lo.x, b0lo.y, b0lo.z, b0lo.w,
                              b0hi.x, b0hi.y, b0hi.z, b0hi.w};
            uint32_t b1[8] = {b1lo.x, b1lo.y, b1lo.z, b1lo.w,
                              b1hi.x, b1hi.y, b1hi.z, b1hi.w};
            #pragma unroll
            for (int nf = 0; nf < 8; nf++) {
                mma_tf32(acc[nf][0], acc[nf][1], acc[nf][2], acc[nf][3],
                         A02.x, A13.x, A02.y, A13.y, b0[nf], b1[nf]);
            }
        }
        __syncthreads();   // done reading Z_s before next stage1 overwrites
    }

    // ---- epilogue: BN+bias into sO[o][tw] (reuses sZ region)
    {
        const int r0 = m0 + (lane >> 2);
        #pragma unroll
        for (int nf = 0; nf < 8; nf++) {
            int o0 = nf * 8 + 2 * (lane & 3);
            float s0 = sBN[64 + o0],     b0v = sBN[o0],     z0 = sBN[128 + o0];
            float s1 = sBN[64 + o0 + 1], b1v = sBN[o0 + 1], z1 = sBN[128 + o0 + 1];
            sO[o0 * 128 + r0]           = (acc[nf][0] + b0v) * s0 + z0;
            sO[(o0 + 1) * 128 + r0]     = (acc[nf][1] + b1v) * s1 + z1;
            sO[o0 * 128 + r0 + 8]       = (acc[nf][2] + b0v) * s0 + z0;
            sO[(o0 + 1) * 128 + r0 + 8] = (acc[nf][3] + b1v) * s1 + z1;
        }
    }
    __syncthreads();

    for (int idx = tid; idx < 64 * 32; idx += 256) {
        int c = idx >> 5, q = idx & 31;
        float4 yv = reinterpret_cast<const float4*>(sO + c * 128)[q];
        float4 xv = reinterpret_cast<const float4*>(sX + c * 128)[q];
        yv.x += xv.x; yv.y += xv.y; yv.z += xv.z; yv.w += xv.w;
        reinterpret_cast<float4*>(out + (size_t)(n * 64 + c) * (T_ * V_) + t0 * V_)[q] = yv;
    }
}

extern "C" void kernel_launch(void* const* d_in, const int* in_sizes, int n_in,
                              void* d_out, int out_size)
{
    const float* x      = (const float*)d_in[0];
    const float* A_base = (const float*)d_in[1];
    const float* PA     = (const float*)d_in[2];
    const float* Wa     = (const float*)d_in[3];
    const float* ba     = (const float*)d_in[4];
    const float* Wb     = (const float*)d_in[5];
    const float* bb     = (const float*)d_in[6];
    const float* Wd     = (const float*)d_in[7];
    const float* bd     = (const float*)d_in[8];
    const float* gamma  = (const float*)d_in[9];
    const float* beta   = (const float*)d_in[10];
    float* out = (float*)d_out;

    const int smemA = (1024 * 2 + 16384 + 4096 * 2) * sizeof(float);  // 106496 B
    const int smemB = 108544;                                         // bytes

    cudaFuncSetAttribute(attn_kernel, cudaFuncAttributeMaxDynamicSharedMemorySize, smemA);
    cudaFuncSetAttribute(out_kernel,  cudaFuncAttributeMaxDynamicSharedMemorySize, smemB);

    attn_kernel<<<N_ * S_, 256, smemA>>>(x, A_base, PA, Wa, ba, Wb, bb);
    out_kernel<<<dim3(T_ / 8, N_), 256, smemB>>>(x, Wd, bd, gamma, beta, out);
}